// round 5
// baseline (speedup 1.0000x reference)
#include <cuda_runtime.h>

// LIF neuron, T=4 unrolled, 4 neurons (float4s) per thread.
// Layout [B, N, T], T innermost -> one float4 per neuron.
// Front-batched 8x LDG.E.128 (MLP_p1=8), streaming hints (read-once/
// write-once), exact-division fast path with zero predicates.
// Workload is at the HBM3e streaming ceiling (~88% DRAM SOL, ~7.0 TB/s).

#define TAU 0.25f

__device__ __forceinline__ float4 lif4(float4 xv, float4 lv, float thre)
{
    float4 ov;
    float u = xv.x + lv.x;                 // t=0: u0=0 -> no decay term
    float o = (u > thre) ? u : 0.0f;
    ov.x = o;
    float reset = (o > thre) ? 0.0f : 1.0f;
    u = TAU * u * reset + xv.y + lv.y;     // t=1
    o = (u > thre) ? u : 0.0f;
    ov.y = o;
    reset = (o > thre) ? 0.0f : 1.0f;
    u = TAU * u * reset + xv.z + lv.z;     // t=2
    o = (u > thre) ? u : 0.0f;
    ov.z = o;
    reset = (o > thre) ? 0.0f : 1.0f;
    u = TAU * u * reset + xv.w + lv.w;     // t=3
    o = (u > thre) ? u : 0.0f;
    ov.w = o;
    return ov;
}

// Fast path: grid*blockDim*4 == n exactly; no predicates.
__global__ __launch_bounds__(256) void lif_kernel_x4(
    const float4* __restrict__ x,
    const float4* __restrict__ lat,
    const float* __restrict__ w,
    float4* __restrict__ out)
{
    int base = blockIdx.x * (blockDim.x * 4) + threadIdx.x;
    int i0 = base;
    int i1 = base + blockDim.x;
    int i2 = base + blockDim.x * 2;
    int i3 = base + blockDim.x * 3;

    const float thre = tanhf(w[0]);

    // Front-batch all 8 loads (read-once: evict-first)
    float4 x0 = __ldcs(&x[i0]);
    float4 l0 = __ldcs(&lat[i0]);
    float4 x1 = __ldcs(&x[i1]);
    float4 l1 = __ldcs(&lat[i1]);
    float4 x2 = __ldcs(&x[i2]);
    float4 l2 = __ldcs(&lat[i2]);
    float4 x3 = __ldcs(&x[i3]);
    float4 l3 = __ldcs(&lat[i3]);

    __stcs(&out[i0], lif4(x0, l0, thre));
    __stcs(&out[i1], lif4(x1, l1, thre));
    __stcs(&out[i2], lif4(x2, l2, thre));
    __stcs(&out[i3], lif4(x3, l3, thre));
}

// Fallback: one float4 per thread, predicated (general sizes).
__global__ __launch_bounds__(256) void lif_kernel_f4(
    const float4* __restrict__ x,
    const float4* __restrict__ lat,
    const float* __restrict__ w,
    float4* __restrict__ out,
    int n)
{
    int i = blockIdx.x * blockDim.x + threadIdx.x;
    if (i >= n) return;
    const float thre = tanhf(w[0]);
    float4 xv = __ldcs(&x[i]);
    float4 lv = __ldcs(&lat[i]);
    __stcs(&out[i], lif4(xv, lv, thre));
}

extern "C" void kernel_launch(void* const* d_in, const int* in_sizes, int n_in,
                              void* d_out, int out_size)
{
    const float4* x   = (const float4*)d_in[0];  // [B, N, T] float32, T=4
    const float4* lat = (const float4*)d_in[1];
    const float*  w   = (const float*)d_in[2];   // scalar
    float4* out = (float4*)d_out;

    int n = in_sizes[0] / 4;     // neurons (B*N); one float4 each
    int block = 256;
    int per_block = block * 4;   // 4 neurons per thread

    if (n % per_block == 0) {
        lif_kernel_x4<<<n / per_block, block>>>(x, lat, w, out);
    } else {
        lif_kernel_f4<<<(n + block - 1) / block, block>>>(x, lat, w, out, n);
    }
}

// round 6
// speedup vs baseline: 1.0125x; 1.0125x over previous
#include <cuda_runtime.h>

// LIF neuron, T=4 unrolled, 2 neurons (float4s) per thread, block=512.
// Layout [B, N, T], T innermost -> one float4 per neuron.
// Front-batched 4x LDG.E.128, streaming hints (read-once/write-once),
// exact-division fast path with zero predicates.
// This workload is at the HBM3e mixed-R/W streaming ceiling:
// every variant measures ~108.6-110.4us kernel @ 87-88% DRAM SOL (~7.0 TB/s).
// Minimum traffic = 768 MB (512 read + 256 write), provably irreducible.

#define TAU 0.25f

__device__ __forceinline__ float4 lif4(float4 xv, float4 lv, float thre)
{
    float4 ov;
    float u = xv.x + lv.x;                 // t=0: u0=0 -> no decay term
    float o = (u > thre) ? u : 0.0f;
    ov.x = o;
    float reset = (o > thre) ? 0.0f : 1.0f;
    u = TAU * u * reset + xv.y + lv.y;     // t=1
    o = (u > thre) ? u : 0.0f;
    ov.y = o;
    reset = (o > thre) ? 0.0f : 1.0f;
    u = TAU * u * reset + xv.z + lv.z;     // t=2
    o = (u > thre) ? u : 0.0f;
    ov.z = o;
    reset = (o > thre) ? 0.0f : 1.0f;
    u = TAU * u * reset + xv.w + lv.w;     // t=3
    o = (u > thre) ? u : 0.0f;
    ov.w = o;
    return ov;
}

// Fast path: grid*blockDim*2 == n exactly; no predicates.
__global__ __launch_bounds__(512) void lif_kernel_exact(
    const float4* __restrict__ x,
    const float4* __restrict__ lat,
    const float* __restrict__ w,
    float4* __restrict__ out)
{
    int i0 = blockIdx.x * (blockDim.x * 2) + threadIdx.x;
    int i1 = i0 + blockDim.x;   // second contiguous 512B warp segment

    const float thre = tanhf(w[0]);

    // Front-batch all 4 loads (read-once: evict-first)
    float4 x0 = __ldcs(&x[i0]);
    float4 l0 = __ldcs(&lat[i0]);
    float4 x1 = __ldcs(&x[i1]);
    float4 l1 = __ldcs(&lat[i1]);

    __stcs(&out[i0], lif4(x0, l0, thre));
    __stcs(&out[i1], lif4(x1, l1, thre));
}

// Fallback: one float4 per thread, predicated (general sizes).
__global__ __launch_bounds__(512) void lif_kernel_f4(
    const float4* __restrict__ x,
    const float4* __restrict__ lat,
    const float* __restrict__ w,
    float4* __restrict__ out,
    int n)
{
    int i = blockIdx.x * blockDim.x + threadIdx.x;
    if (i >= n) return;
    const float thre = tanhf(w[0]);
    float4 xv = __ldcs(&x[i]);
    float4 lv = __ldcs(&lat[i]);
    __stcs(&out[i], lif4(xv, lv, thre));
}

extern "C" void kernel_launch(void* const* d_in, const int* in_sizes, int n_in,
                              void* d_out, int out_size)
{
    const float4* x   = (const float4*)d_in[0];  // [B, N, T] float32, T=4
    const float4* lat = (const float4*)d_in[1];
    const float*  w   = (const float*)d_in[2];   // scalar
    float4* out = (float4*)d_out;

    int n = in_sizes[0] / 4;     // neurons (B*N); one float4 each
    int block = 512;
    int per_block = block * 2;   // 2 neurons per thread

    if (n % per_block == 0) {
        lif_kernel_exact<<<n / per_block, block>>>(x, lat, w, out);
    } else {
        lif_kernel_f4<<<(n + block - 1) / block, block>>>(x, lat, w, out, n);
    }
}